// round 2
// baseline (speedup 1.0000x reference)
#include <cuda_runtime.h>
#include <cstdint>

// Problem constants (fixed instance)
#define NN   100000
#define NPAD 100096          // 782 * 128, padded so GEMM tiles never fault
#define C    256
#define NSETS 4

// Persistent scratch (device globals — no allocation allowed)
__device__ float g_h[(size_t)NSETS * NPAD * C];   // ~410 MB: H_s = x @ (W_s ⊙ p_s)
__device__ float g_dis[NSETS * NN];               // rsqrt(deg)
__device__ int   g_deg[NSETS * NN];
__device__ float g_wcat[C * (NSETS * C)];         // [256][1024] fused weights
__device__ float g_bsum[C];

// ---------------------------------------------------------------------------
// Prep: fused weights Wcat[k][s*256+n] = W_s[k][n]*p_{s+2}[n], bias term, deg=1
// ---------------------------------------------------------------------------
__global__ void prep_kernel(const float* __restrict__ W1, const float* __restrict__ W2,
                            const float* __restrict__ W3, const float* __restrict__ W4,
                            const float* __restrict__ b1, const float* __restrict__ b2,
                            const float* __restrict__ b3, const float* __restrict__ b4,
                            const float* __restrict__ p2, const float* __restrict__ p3,
                            const float* __restrict__ p4, const float* __restrict__ p5) {
    int k = blockIdx.x;       // input channel 0..255
    int n = threadIdx.x;      // output channel 0..255
    g_wcat[k * 1024 + 0 * 256 + n] = W1[k * 256 + n] * p2[n];
    g_wcat[k * 1024 + 1 * 256 + n] = W2[k * 256 + n] * p3[n];
    g_wcat[k * 1024 + 2 * 256 + n] = W3[k * 256 + n] * p4[n];
    g_wcat[k * 1024 + 3 * 256 + n] = W4[k * 256 + n] * p5[n];
    if (k == 0)
        g_bsum[n] = b1[n] * p2[n] + b2[n] * p3[n] + b3[n] * p4[n] + b4[n] * p5[n];
    // degree init to 1 (self loop)
    int idx = k * 256 + n;
    for (int i = idx; i < NSETS * NN; i += 256 * 256) g_deg[i] = 1;
}

// ---------------------------------------------------------------------------
// Degree count: deg_s[col] += 1 per edge
// ---------------------------------------------------------------------------
__global__ void deg_kernel(const int* __restrict__ e0, const int* __restrict__ e1,
                           const int* __restrict__ e2, const int* __restrict__ e3, int E) {
    int s = blockIdx.y;
    int e = blockIdx.x * blockDim.x + threadIdx.x;
    if (e >= E) return;
    const int* eg = (s == 0) ? e0 : (s == 1) ? e1 : (s == 2) ? e2 : e3;
    int col = __ldg(&eg[E + e]);
    atomicAdd(&g_deg[s * NN + col], 1);
}

__global__ void dis_kernel() {
    int i = blockIdx.x * blockDim.x + threadIdx.x;
    if (i < NSETS * NN) g_dis[i] = rsqrtf((float)g_deg[i]);
}

// ---------------------------------------------------------------------------
// tf32 GEMM: H[s][v][n] = sum_k x[v][k] * Wcat[k][s*256+n]
// M=100000 (pad 100096), N=1024, K=256.  CTA tile 128x128, BK=32, 8 warps.
// ---------------------------------------------------------------------------
#define BM 128
#define BN 128
#define BK 32
#define LDA 36     // pad: bank = (4*row + col) % 32 -> conflict-free frag loads
#define LDB 136    // pad: bank = (8*row + col) % 32 -> conflict-free frag loads

static constexpr int SMEM_BYTES = (2 * BM * LDA + 2 * BK * LDB) * 4;  // 71680

__device__ __forceinline__ void cp_async16(float* smem_ptr, const float* gmem_ptr, int src_bytes) {
    uint32_t saddr = (uint32_t)__cvta_generic_to_shared(smem_ptr);
    asm volatile("cp.async.cg.shared.global [%0], [%1], 16, %2;\n"
                 :: "r"(saddr), "l"(gmem_ptr), "r"(src_bytes));
}
__device__ __forceinline__ uint32_t f2tf32(float f) {
    uint32_t r;
    asm("cvt.rna.tf32.f32 %0, %1;" : "=r"(r) : "f"(f));
    return r;
}

__global__ __launch_bounds__(256) void gemm_kernel(const float* __restrict__ x, int n_rows) {
    extern __shared__ float sm[];
    float* Asm[2] = { sm, sm + BM * LDA };
    float* Bsm[2] = { sm + 2 * BM * LDA, sm + 2 * BM * LDA + BK * LDB };

    const int tid   = threadIdx.x;
    const int lane  = tid & 31;
    const int warp  = tid >> 5;
    const int warpM = warp >> 2;   // 0..1  (64 rows each)
    const int warpN = warp & 3;    // 0..3  (32 cols each)
    const int m0 = blockIdx.x * BM;
    const int n0 = blockIdx.y * BN;     // 0..1023, within one set (BN=128 | 256)

    float acc[4][4][4];
#pragma unroll
    for (int i = 0; i < 4; i++)
#pragma unroll
        for (int j = 0; j < 4; j++)
#pragma unroll
            for (int k = 0; k < 4; k++) acc[i][j][k] = 0.f;

    auto loadA = [&](int buf, int kb) {
#pragma unroll
        for (int p = 0; p < 4; p++) {
            int idx = tid + p * 256;       // 1024 float4s: 128 rows x 8
            int row = idx >> 3;
            int c4  = idx & 7;
            int gr  = m0 + row;
            const float* src = x + (size_t)gr * C + kb + c4 * 4;
            cp_async16(&Asm[buf][row * LDA + c4 * 4], src, gr < n_rows ? 16 : 0);
        }
    };
    auto loadB = [&](int buf, int kb) {
#pragma unroll
        for (int p = 0; p < 4; p++) {
            int idx = tid + p * 256;       // 1024 float4s: 32 rows x 32
            int row = idx >> 5;
            int c4  = idx & 31;
            const float* src = g_wcat + (size_t)(kb + row) * 1024 + n0 + c4 * 4;
            cp_async16(&Bsm[buf][row * LDB + c4 * 4], src, 16);
        }
    };

    loadA(0, 0); loadB(0, 0);
    asm volatile("cp.async.commit_group;\n");

#pragma unroll 1
    for (int kc = 0; kc < 8; kc++) {          // K = 256 = 8 * BK
        int cur = kc & 1;
        if (kc < 7) {
            loadA(cur ^ 1, (kc + 1) * BK);
            loadB(cur ^ 1, (kc + 1) * BK);
            asm volatile("cp.async.commit_group;\n");
            asm volatile("cp.async.wait_group 1;\n");
        } else {
            asm volatile("cp.async.wait_group 0;\n");
        }
        __syncthreads();

        const float* Ab = Asm[cur];
        const float* Bb = Bsm[cur];
#pragma unroll
        for (int kk = 0; kk < BK; kk += 8) {
            uint32_t afr[4][4];
#pragma unroll
            for (int mt = 0; mt < 4; mt++) {
                int r = warpM * 64 + mt * 16 + (lane >> 2);
                int c = kk + (lane & 3);
                afr[mt][0] = f2tf32(Ab[r * LDA + c]);
                afr[mt][1] = f2tf32(Ab[(r + 8) * LDA + c]);
                afr[mt][2] = f2tf32(Ab[r * LDA + c + 4]);
                afr[mt][3] = f2tf32(Ab[(r + 8) * LDA + c + 4]);
            }
            uint32_t bfr[4][2];
#pragma unroll
            for (int nt = 0; nt < 4; nt++) {
                int cb = warpN * 32 + nt * 8 + (lane >> 2);
                int k  = kk + (lane & 3);
                bfr[nt][0] = f2tf32(Bb[k * LDB + cb]);
                bfr[nt][1] = f2tf32(Bb[(k + 4) * LDB + cb]);
            }
#pragma unroll
            for (int mt = 0; mt < 4; mt++)
#pragma unroll
                for (int nt = 0; nt < 4; nt++)
                    asm volatile(
                        "mma.sync.aligned.m16n8k8.row.col.f32.tf32.tf32.f32 "
                        "{%0,%1,%2,%3}, {%4,%5,%6,%7}, {%8,%9}, {%0,%1,%2,%3};\n"
                        : "+f"(acc[mt][nt][0]), "+f"(acc[mt][nt][1]),
                          "+f"(acc[mt][nt][2]), "+f"(acc[mt][nt][3])
                        : "r"(afr[mt][0]), "r"(afr[mt][1]), "r"(afr[mt][2]), "r"(afr[mt][3]),
                          "r"(bfr[nt][0]), "r"(bfr[nt][1]));
        }
        __syncthreads();
    }

    // Epilogue: store H_s
    int s  = n0 >> 8;
    int nl = n0 & 255;
    float* H = g_h + (size_t)s * NPAD * C;
#pragma unroll
    for (int mt = 0; mt < 4; mt++) {
        int r0 = m0 + warpM * 64 + mt * 16 + (lane >> 2);
#pragma unroll
        for (int nt = 0; nt < 4; nt++) {
            int cc = nl + warpN * 32 + nt * 8 + 2 * (lane & 3);
            if (r0 < n_rows)
                *(float2*)&H[(size_t)r0 * C + cc] = make_float2(acc[mt][nt][0], acc[mt][nt][1]);
            if (r0 + 8 < n_rows)
                *(float2*)&H[(size_t)(r0 + 8) * C + cc] = make_float2(acc[mt][nt][2], acc[mt][nt][3]);
        }
    }
}

// ---------------------------------------------------------------------------
// Self-loop + base: out[v][c] = x[v][0]*(t0*p0 + t1*p1) + bsum + Σ_s H_s[v][c]/deg_s[v]
// ---------------------------------------------------------------------------
__global__ void self_kernel(const float* __restrict__ x, const float* __restrict__ t0,
                            const float* __restrict__ t1, const float* __restrict__ p0,
                            const float* __restrict__ p1, float* __restrict__ out) {
    int v = blockIdx.x;
    int c = threadIdx.x;
    float x0 = __ldg(&x[(size_t)v * C]);
    float a0 = x0 * __ldg(&t0[v]);
    float a1 = x0 * __ldg(&t1[v]);
    float acc = a0 * __ldg(&p0[c]) + a1 * __ldg(&p1[c]) + g_bsum[c];
#pragma unroll
    for (int s = 0; s < NSETS; s++) {
        float invd = 1.0f / (float)g_deg[s * NN + v];
        acc += invd * g_h[((size_t)s * NPAD + v) * C + c];
    }
    out[(size_t)v * C + c] = acc;
}

// ---------------------------------------------------------------------------
// Edge scatter: out[col] += dis[row]*dis[col] * H_s[row]   (1 warp / edge)
// ---------------------------------------------------------------------------
__global__ void scatter_kernel(const int* __restrict__ e0, const int* __restrict__ e1,
                               const int* __restrict__ e2, const int* __restrict__ e3,
                               int E, float* __restrict__ out) {
    int s = blockIdx.y;
    int e = blockIdx.x * 8 + (threadIdx.x >> 5);
    if (e >= E) return;
    int lane = threadIdx.x & 31;
    const int* eg = (s == 0) ? e0 : (s == 1) ? e1 : (s == 2) ? e2 : e3;
    int r = __ldg(&eg[e]);
    int c = __ldg(&eg[E + e]);
    float w = g_dis[s * NN + r] * g_dis[s * NN + c];
    const float4* src = (const float4*)(g_h + ((size_t)s * NPAD + r) * C);
    float4* dst = (float4*)(out + (size_t)c * C);
#pragma unroll
    for (int j = 0; j < 2; j++) {
        float4 v = __ldg(&src[lane + j * 32]);
        float4 m = make_float4(v.x * w, v.y * w, v.z * w, v.w * w);
        atomicAdd(&dst[lane + j * 32], m);   // vector RED, sm_90+
    }
}

// ---------------------------------------------------------------------------
extern "C" void kernel_launch(void* const* d_in, const int* in_sizes, int n_in,
                              void* d_out, int out_size) {
    const float* x   = (const float*)d_in[0];
    const int* e00   = (const int*)d_in[1];
    const int* e01   = (const int*)d_in[2];
    const int* e10   = (const int*)d_in[3];
    const int* e11   = (const int*)d_in[4];
    const float* t0  = (const float*)d_in[5];
    const float* t1  = (const float*)d_in[6];
    const float* W1  = (const float*)d_in[7];
    const float* b1  = (const float*)d_in[8];
    const float* W2  = (const float*)d_in[9];
    const float* b2  = (const float*)d_in[10];
    const float* W3  = (const float*)d_in[11];
    const float* b3  = (const float*)d_in[12];
    const float* W4  = (const float*)d_in[13];
    const float* b4  = (const float*)d_in[14];
    const float* p0  = (const float*)d_in[15];
    const float* p1  = (const float*)d_in[16];
    const float* p2  = (const float*)d_in[17];
    const float* p3  = (const float*)d_in[18];
    const float* p4  = (const float*)d_in[19];
    const float* p5  = (const float*)d_in[20];

    const int E      = in_sizes[1] / 2;      // 500000
    const int n_rows = in_sizes[0] / C;      // 100000

    cudaFuncSetAttribute(gemm_kernel, cudaFuncAttributeMaxDynamicSharedMemorySize, SMEM_BYTES);

    prep_kernel<<<256, 256>>>(W1, W2, W3, W4, b1, b2, b3, b4, p2, p3, p4, p5);

    dim3 dgrid((E + 255) / 256, NSETS);
    deg_kernel<<<dgrid, 256>>>(e00, e01, e10, e11, E);

    dis_kernel<<<(NSETS * NN + 255) / 256, 256>>>();

    dim3 ggrid((n_rows + BM - 1) / BM, (NSETS * C) / BN);
    gemm_kernel<<<ggrid, 256, SMEM_BYTES>>>(x, n_rows);

    self_kernel<<<n_rows, C>>>(x, t0, t1, p0, p1, (float*)d_out);

    dim3 sgrid((E + 7) / 8, NSETS);
    scatter_kernel<<<sgrid, 256>>>(e00, e01, e10, e11, E, (float*)d_out);
}

// round 6
// speedup vs baseline: 1.1247x; 1.1247x over previous
#include <cuda_runtime.h>
#include <cuda_fp16.h>
#include <cstdint>

// Problem constants (fixed instance)
#define NN   100000
#define NPAD 100096          // 782 * 128
#define C    256
#define NSETS 4

// Persistent scratch (device globals — no allocation allowed)
__device__ __half g_h[(size_t)NSETS * NPAD * C];  // ~205 MB: H_s = x @ (W_s ⊙ p_s), fp16
__device__ float g_dis[NSETS * NN];               // rsqrt(deg)
__device__ int   g_deg[NSETS * NN];
__device__ float g_wcat[C * (NSETS * C)];         // [256][1024] fused weights
__device__ float g_bsum[C];

// ---------------------------------------------------------------------------
// Prep: fused weights Wcat[k][s*256+n] = W_s[k][n]*p_{s+2}[n], bias term, deg=1
// ---------------------------------------------------------------------------
__global__ void prep_kernel(const float* __restrict__ W1, const float* __restrict__ W2,
                            const float* __restrict__ W3, const float* __restrict__ W4,
                            const float* __restrict__ b1, const float* __restrict__ b2,
                            const float* __restrict__ b3, const float* __restrict__ b4,
                            const float* __restrict__ p2, const float* __restrict__ p3,
                            const float* __restrict__ p4, const float* __restrict__ p5) {
    int k = blockIdx.x;       // input channel 0..255
    int n = threadIdx.x;      // output channel 0..255
    g_wcat[k * 1024 + 0 * 256 + n] = W1[k * 256 + n] * p2[n];
    g_wcat[k * 1024 + 1 * 256 + n] = W2[k * 256 + n] * p3[n];
    g_wcat[k * 1024 + 2 * 256 + n] = W3[k * 256 + n] * p4[n];
    g_wcat[k * 1024 + 3 * 256 + n] = W4[k * 256 + n] * p5[n];
    if (k == 0)
        g_bsum[n] = b1[n] * p2[n] + b2[n] * p3[n] + b3[n] * p4[n] + b4[n] * p5[n];
    // degree init to 1 (self loop)
    int idx = k * 256 + n;
    for (int i = idx; i < NSETS * NN; i += 256 * 256) g_deg[i] = 1;
}

// ---------------------------------------------------------------------------
// Degree count
// ---------------------------------------------------------------------------
__global__ void deg_kernel(const int* __restrict__ e0, const int* __restrict__ e1,
                           const int* __restrict__ e2, const int* __restrict__ e3, int E) {
    int s = blockIdx.y;
    int e = blockIdx.x * blockDim.x + threadIdx.x;
    if (e >= E) return;
    const int* eg = (s == 0) ? e0 : (s == 1) ? e1 : (s == 2) ? e2 : e3;
    int col = __ldg(&eg[E + e]);
    atomicAdd(&g_deg[s * NN + col], 1);
}

__global__ void dis_kernel() {
    int i = blockIdx.x * blockDim.x + threadIdx.x;
    if (i < NSETS * NN) g_dis[i] = rsqrtf((float)g_deg[i]);
}

// ---------------------------------------------------------------------------
// tf32 GEMM: H[s][v][n] = sum_k x[v][k] * Wcat[k][s*256+n], fp16 output
// M=100000 (pad 100096), N=1024, K=256.  CTA tile 128x128, BK=32, 8 warps.
// grid = (8 N-tiles, 782 M-tiles): consecutive CTAs share the A tile -> L2 reuse.
// ---------------------------------------------------------------------------
#define BM 128
#define BN 128
#define BK 32
#define LDA 36
#define LDB 136

static constexpr int SMEM_BYTES = (2 * BM * LDA + 2 * BK * LDB) * 4;  // 71680

__device__ __forceinline__ void cp_async16(float* smem_ptr, const float* gmem_ptr, int src_bytes) {
    uint32_t saddr = (uint32_t)__cvta_generic_to_shared(smem_ptr);
    asm volatile("cp.async.cg.shared.global [%0], [%1], 16, %2;\n"
                 :: "r"(saddr), "l"(gmem_ptr), "r"(src_bytes));
}
__device__ __forceinline__ uint32_t f2tf32(float f) {
    uint32_t r;
    asm("cvt.rna.tf32.f32 %0, %1;" : "=r"(r) : "f"(f));
    return r;
}

__global__ __launch_bounds__(256, 2) void gemm_kernel(const float* __restrict__ x, int n_rows) {
    extern __shared__ float sm[];
    float* Asm[2] = { sm, sm + BM * LDA };
    float* Bsm[2] = { sm + 2 * BM * LDA, sm + 2 * BM * LDA + BK * LDB };

    const int tid   = threadIdx.x;
    const int lane  = tid & 31;
    const int warp  = tid >> 5;
    const int warpM = warp >> 2;   // 0..1  (64 rows each)
    const int warpN = warp & 3;    // 0..3  (32 cols each)
    const int m0 = blockIdx.y * BM;
    const int n0 = blockIdx.x * BN;     // 0..1023

    float acc[4][4][4];
#pragma unroll
    for (int i = 0; i < 4; i++)
#pragma unroll
        for (int j = 0; j < 4; j++)
#pragma unroll
            for (int k = 0; k < 4; k++) acc[i][j][k] = 0.f;

    auto loadA = [&](int buf, int kb) {
#pragma unroll
        for (int p = 0; p < 4; p++) {
            int idx = tid + p * 256;       // 1024 float4s: 128 rows x 8
            int row = idx >> 3;
            int c4  = idx & 7;
            int gr  = m0 + row;
            const float* src = x + (size_t)gr * C + kb + c4 * 4;
            cp_async16(&Asm[buf][row * LDA + c4 * 4], src, gr < n_rows ? 16 : 0);
        }
    };
    auto loadB = [&](int buf, int kb) {
#pragma unroll
        for (int p = 0; p < 4; p++) {
            int idx = tid + p * 256;       // 1024 float4s: 32 rows x 32
            int row = idx >> 5;
            int c4  = idx & 31;
            const float* src = g_wcat + (size_t)(kb + row) * 1024 + n0 + c4 * 4;
            cp_async16(&Bsm[buf][row * LDB + c4 * 4], src, 16);
        }
    };

    loadA(0, 0); loadB(0, 0);
    asm volatile("cp.async.commit_group;\n");

#pragma unroll 1
    for (int kc = 0; kc < 8; kc++) {          // K = 256 = 8 * BK
        int cur = kc & 1;
        if (kc < 7) {
            loadA(cur ^ 1, (kc + 1) * BK);
            loadB(cur ^ 1, (kc + 1) * BK);
            asm volatile("cp.async.commit_group;\n");
            asm volatile("cp.async.wait_group 1;\n");
        } else {
            asm volatile("cp.async.wait_group 0;\n");
        }
        __syncthreads();

        const float* Ab = Asm[cur];
        const float* Bb = Bsm[cur];
#pragma unroll
        for (int kk = 0; kk < BK; kk += 8) {
            uint32_t afr[4][4];
#pragma unroll
            for (int mt = 0; mt < 4; mt++) {
                int r = warpM * 64 + mt * 16 + (lane >> 2);
                int c = kk + (lane & 3);
                afr[mt][0] = f2tf32(Ab[r * LDA + c]);
                afr[mt][1] = f2tf32(Ab[(r + 8) * LDA + c]);
                afr[mt][2] = f2tf32(Ab[r * LDA + c + 4]);
                afr[mt][3] = f2tf32(Ab[(r + 8) * LDA + c + 4]);
            }
            uint32_t bfr[4][2];
#pragma unroll
            for (int nt = 0; nt < 4; nt++) {
                int cb = warpN * 32 + nt * 8 + (lane >> 2);
                int k  = kk + (lane & 3);
                bfr[nt][0] = f2tf32(Bb[k * LDB + cb]);
                bfr[nt][1] = f2tf32(Bb[(k + 4) * LDB + cb]);
            }
#pragma unroll
            for (int mt = 0; mt < 4; mt++)
#pragma unroll
                for (int nt = 0; nt < 4; nt++)
                    asm volatile(
                        "mma.sync.aligned.m16n8k8.row.col.f32.tf32.tf32.f32 "
                        "{%0,%1,%2,%3}, {%4,%5,%6,%7}, {%8,%9}, {%0,%1,%2,%3};\n"
                        : "+f"(acc[mt][nt][0]), "+f"(acc[mt][nt][1]),
                          "+f"(acc[mt][nt][2]), "+f"(acc[mt][nt][3])
                        : "r"(afr[mt][0]), "r"(afr[mt][1]), "r"(afr[mt][2]), "r"(afr[mt][3]),
                          "r"(bfr[nt][0]), "r"(bfr[nt][1]));
        }
        __syncthreads();
    }

    // Epilogue: store H_s as fp16
    int s  = n0 >> 8;
    int nl = n0 & 255;
    __half* H = g_h + (size_t)s * NPAD * C;
#pragma unroll
    for (int mt = 0; mt < 4; mt++) {
        int r0 = m0 + warpM * 64 + mt * 16 + (lane >> 2);
#pragma unroll
        for (int nt = 0; nt < 4; nt++) {
            int cc = nl + warpN * 32 + nt * 8 + 2 * (lane & 3);
            if (r0 < n_rows)
                *(__half2*)&H[(size_t)r0 * C + cc] = __floats2half2_rn(acc[mt][nt][0], acc[mt][nt][1]);
            if (r0 + 8 < n_rows)
                *(__half2*)&H[(size_t)(r0 + 8) * C + cc] = __floats2half2_rn(acc[mt][nt][2], acc[mt][nt][3]);
        }
    }
}

// ---------------------------------------------------------------------------
// Self-loop + base: out[v][c] = x[v][0]*(t0*p0+t1*p1) + bsum + Σ_s H_s[v][c]/deg_s[v]
// One block of 128 threads per node; each thread does 2 channels via half2.
// ---------------------------------------------------------------------------
__global__ __launch_bounds__(128) void self_kernel(
        const float* __restrict__ x, const float* __restrict__ t0,
        const float* __restrict__ t1, const float* __restrict__ p0,
        const float* __restrict__ p1, float* __restrict__ out) {
    int v = blockIdx.x;
    int c = threadIdx.x * 2;
    float x0 = __ldg(&x[(size_t)v * C]);
    float a0 = x0 * __ldg(&t0[v]);
    float a1 = x0 * __ldg(&t1[v]);
    float accx = a0 * __ldg(&p0[c])     + a1 * __ldg(&p1[c])     + g_bsum[c];
    float accy = a0 * __ldg(&p0[c + 1]) + a1 * __ldg(&p1[c + 1]) + g_bsum[c + 1];
#pragma unroll
    for (int s = 0; s < NSETS; s++) {
        float invd = 1.0f / (float)g_deg[s * NN + v];
        __half2 h = *(const __half2*)&g_h[((size_t)s * NPAD + v) * C + c];
        float2 f = __half22float2(h);
        accx += invd * f.x;
        accy += invd * f.y;
    }
    *(float2*)&out[(size_t)v * C + c] = make_float2(accx, accy);
}

// ---------------------------------------------------------------------------
// Edge scatter: out[col] += dis[row]*dis[col] * H_s[row]   (1 warp / edge)
// fp16 gather (16B/lane), fp32 vector atomics (2x float4/lane)
// ---------------------------------------------------------------------------
__global__ __launch_bounds__(256) void scatter_kernel(
        const int* __restrict__ e0, const int* __restrict__ e1,
        const int* __restrict__ e2, const int* __restrict__ e3,
        int E, float* __restrict__ out) {
    int s = blockIdx.y;
    int e = blockIdx.x * 8 + (threadIdx.x >> 5);
    if (e >= E) return;
    int lane = threadIdx.x & 31;
    const int* eg = (s == 0) ? e0 : (s == 1) ? e1 : (s == 2) ? e2 : e3;
    int r = __ldg(&eg[e]);
    int c = __ldg(&eg[E + e]);
    float w = g_dis[s * NN + r] * g_dis[s * NN + c];

    const uint4* src = (const uint4*)(g_h + ((size_t)s * NPAD + r) * C);
    uint4 v = __ldg(&src[lane]);           // 8 halves
    __half2* hp = (__half2*)&v;
    float2 f0 = __half22float2(hp[0]);
    float2 f1 = __half22float2(hp[1]);
    float2 f2 = __half22float2(hp[2]);
    float2 f3 = __half22float2(hp[3]);

    float4* dst = (float4*)(out + (size_t)c * C);
    atomicAdd(&dst[lane * 2],     make_float4(f0.x * w, f0.y * w, f1.x * w, f1.y * w));
    atomicAdd(&dst[lane * 2 + 1], make_float4(f2.x * w, f2.y * w, f3.x * w, f3.y * w));
}

// ---------------------------------------------------------------------------
extern "C" void kernel_launch(void* const* d_in, const int* in_sizes, int n_in,
                              void* d_out, int out_size) {
    const float* x   = (const float*)d_in[0];
    const int* e00   = (const int*)d_in[1];
    const int* e01   = (const int*)d_in[2];
    const int* e10   = (const int*)d_in[3];
    const int* e11   = (const int*)d_in[4];
    const float* t0  = (const float*)d_in[5];
    const float* t1  = (const float*)d_in[6];
    const float* W1  = (const float*)d_in[7];
    const float* b1  = (const float*)d_in[8];
    const float* W2  = (const float*)d_in[9];
    const float* b2  = (const float*)d_in[10];
    const float* W3  = (const float*)d_in[11];
    const float* b3  = (const float*)d_in[12];
    const float* W4  = (const float*)d_in[13];
    const float* b4  = (const float*)d_in[14];
    const float* p0  = (const float*)d_in[15];
    const float* p1  = (const float*)d_in[16];
    const float* p2  = (const float*)d_in[17];
    const float* p3  = (const float*)d_in[18];
    const float* p4  = (const float*)d_in[19];
    const float* p5  = (const float*)d_in[20];

    const int E      = in_sizes[1] / 2;      // 500000
    const int n_rows = in_sizes[0] / C;      // 100000

    cudaFuncSetAttribute(gemm_kernel, cudaFuncAttributeMaxDynamicSharedMemorySize, SMEM_BYTES);

    prep_kernel<<<256, 256>>>(W1, W2, W3, W4, b1, b2, b3, b4, p2, p3, p4, p5);

    dim3 dgrid((E + 255) / 256, NSETS);
    deg_kernel<<<dgrid, 256>>>(e00, e01, e10, e11, E);

    dis_kernel<<<(NSETS * NN + 255) / 256, 256>>>();

    dim3 ggrid((NSETS * C) / BN, (n_rows + BM - 1) / BM);
    gemm_kernel<<<ggrid, 256, SMEM_BYTES>>>(x, n_rows);

    self_kernel<<<n_rows, 128>>>(x, t0, t1, p0, p1, (float*)d_out);

    dim3 sgrid((E + 7) / 8, NSETS);
    scatter_kernel<<<sgrid, 256>>>(e00, e01, e10, e11, E, (float*)d_out);
}

// round 7
// speedup vs baseline: 1.5832x; 1.4077x over previous
#include <cuda_runtime.h>
#include <cuda_fp16.h>
#include <cstdint>

// Problem constants (fixed instance)
#define NN    100000
#define NPAD  100096          // 782 * 128
#define C     256
#define NSETS 4
#define EMAX  500000
#define NT    (NSETS * NN)    // 400000 (deg/offset table size)
#define NBLK  ((NT + 1023) / 1024)   // 391 scan blocks

// Persistent scratch (device globals — no allocation allowed)
__device__ __half   g_h[(size_t)NSETS * NPAD * C];   // ~205 MB fp16 H_s
__device__ uint32_t g_xtf[(size_t)NPAD * C];         // ~102 MB x pre-converted to tf32 bits
__device__ float    g_dis[NT];                       // rsqrt(deg)
__device__ int      g_deg[NT];                       // 1 + in-edge count
__device__ int      g_off[NT];                       // CSR offsets (global over all sets)
__device__ int      g_cursor[NT];                    // fill cursors
__device__ int      g_rows[NSETS * EMAX];            // CSR: source rows bucketed by (s, col)
__device__ int      g_bsums[512];                    // scan block sums
__device__ uint32_t g_wcat[C * (NSETS * C)];         // [256][1024] fused weights, tf32 bits
__device__ float    g_bsum[C];                       // Σ_s b_s ⊙ p_{s+2}

__device__ __forceinline__ uint32_t f2tf32(float f) {
    uint32_t r;
    asm("cvt.rna.tf32.f32 %0, %1;" : "=r"(r) : "f"(f));
    return r;
}

// ---------------------------------------------------------------------------
// Prep: Wcat[k][s*256+n] = tf32(W_s[k][n]*p_{s+2}[n]); bias term; deg init = 1
// ---------------------------------------------------------------------------
__global__ void prep_kernel(const float* __restrict__ W1, const float* __restrict__ W2,
                            const float* __restrict__ W3, const float* __restrict__ W4,
                            const float* __restrict__ b1, const float* __restrict__ b2,
                            const float* __restrict__ b3, const float* __restrict__ b4,
                            const float* __restrict__ p2, const float* __restrict__ p3,
                            const float* __restrict__ p4, const float* __restrict__ p5) {
    int k = blockIdx.x;
    int n = threadIdx.x;
    g_wcat[k * 1024 + 0 * 256 + n] = f2tf32(W1[k * 256 + n] * p2[n]);
    g_wcat[k * 1024 + 1 * 256 + n] = f2tf32(W2[k * 256 + n] * p3[n]);
    g_wcat[k * 1024 + 2 * 256 + n] = f2tf32(W3[k * 256 + n] * p4[n]);
    g_wcat[k * 1024 + 3 * 256 + n] = f2tf32(W4[k * 256 + n] * p5[n]);
    if (k == 0)
        g_bsum[n] = b1[n] * p2[n] + b2[n] * p3[n] + b3[n] * p4[n] + b4[n] * p5[n];
    int idx = k * 256 + n;
    for (int i = idx; i < NT; i += 256 * 256) g_deg[i] = 1;
}

// ---------------------------------------------------------------------------
// x -> tf32 bits (vectorized)
// ---------------------------------------------------------------------------
__global__ void xcvt_kernel(const float* __restrict__ x, int n4) {
    int i = blockIdx.x * blockDim.x + threadIdx.x;
    if (i >= n4) return;
    float4 v = __ldg((const float4*)x + i);
    uint4 o = make_uint4(f2tf32(v.x), f2tf32(v.y), f2tf32(v.z), f2tf32(v.w));
    ((uint4*)g_xtf)[i] = o;
}

// ---------------------------------------------------------------------------
// Degree count
// ---------------------------------------------------------------------------
__global__ void deg_kernel(const int* __restrict__ e0, const int* __restrict__ e1,
                           const int* __restrict__ e2, const int* __restrict__ e3, int E) {
    int s = blockIdx.y;
    int e = blockIdx.x * blockDim.x + threadIdx.x;
    if (e >= E) return;
    const int* eg = (s == 0) ? e0 : (s == 1) ? e1 : (s == 2) ? e2 : e3;
    atomicAdd(&g_deg[s * NN + __ldg(&eg[E + e])], 1);
}

__global__ void dis_kernel() {
    int i = blockIdx.x * blockDim.x + threadIdx.x;
    if (i < NT) g_dis[i] = rsqrtf((float)g_deg[i]);
}

// ---------------------------------------------------------------------------
// Exclusive scan over edge counts (g_deg[i]-1), 3 passes
// ---------------------------------------------------------------------------
__global__ void scanA_kernel() {
    int t = threadIdx.x;
    int base = blockIdx.x * 1024 + t * 4;
    int s = 0;
#pragma unroll
    for (int k = 0; k < 4; k++) {
        int i = base + k;
        if (i < NT) s += g_deg[i] - 1;
    }
    __shared__ int sm[256];
    sm[t] = s;
    __syncthreads();
    for (int d = 128; d > 0; d >>= 1) {
        if (t < d) sm[t] += sm[t + d];
        __syncthreads();
    }
    if (t == 0) g_bsums[blockIdx.x] = sm[0];
}

__global__ void scanB_kernel() {
    int t = threadIdx.x;   // 512 threads
    __shared__ int sm[512];
    int v = (t < NBLK) ? g_bsums[t] : 0;
    sm[t] = v;
    __syncthreads();
    for (int d = 1; d < 512; d <<= 1) {
        int tmp = (t >= d) ? sm[t - d] : 0;
        __syncthreads();
        sm[t] += tmp;
        __syncthreads();
    }
    if (t < NBLK) g_bsums[t] = sm[t] - v;   // exclusive
}

__global__ void scanC_kernel() {
    int t = threadIdx.x;
    int base = blockIdx.x * 1024 + t * 4;
    int a[4], tsum = 0;
#pragma unroll
    for (int k = 0; k < 4; k++) {
        int i = base + k;
        a[k] = (i < NT) ? (g_deg[i] - 1) : 0;
        tsum += a[k];
    }
    __shared__ int sm[256];
    sm[t] = tsum;
    __syncthreads();
    for (int d = 1; d < 256; d <<= 1) {
        int tmp = (t >= d) ? sm[t - d] : 0;
        __syncthreads();
        sm[t] += tmp;
        __syncthreads();
    }
    int run = g_bsums[blockIdx.x] + sm[t] - tsum;
#pragma unroll
    for (int k = 0; k < 4; k++) {
        int i = base + k;
        if (i < NT) {
            g_off[i] = run;
            g_cursor[i] = run;
            run += a[k];
        }
    }
}

// ---------------------------------------------------------------------------
// Bucket edges: g_rows[pos] = source row, grouped by (set, col)
// ---------------------------------------------------------------------------
__global__ void fill_kernel(const int* __restrict__ e0, const int* __restrict__ e1,
                            const int* __restrict__ e2, const int* __restrict__ e3, int E) {
    int s = blockIdx.y;
    int e = blockIdx.x * blockDim.x + threadIdx.x;
    if (e >= E) return;
    const int* eg = (s == 0) ? e0 : (s == 1) ? e1 : (s == 2) ? e2 : e3;
    int row = __ldg(&eg[e]);
    int col = __ldg(&eg[E + e]);
    int pos = atomicAdd(&g_cursor[s * NN + col], 1);
    g_rows[pos] = row;
}

// ---------------------------------------------------------------------------
// tf32 GEMM: H[s][v][n] = sum_k x[v][k] * Wcat[k][s*256+n], fp16 output
// Inputs pre-converted to tf32 bits — no cvt in mainloop.
// ---------------------------------------------------------------------------
#define BM 128
#define BN 128
#define BK 32
#define LDA 36
#define LDB 136

static constexpr int SMEM_BYTES = (2 * BM * LDA + 2 * BK * LDB) * 4;  // 71680

__device__ __forceinline__ void cp_async16(uint32_t* smem_ptr, const uint32_t* gmem_ptr, int src_bytes) {
    uint32_t saddr = (uint32_t)__cvta_generic_to_shared(smem_ptr);
    asm volatile("cp.async.cg.shared.global [%0], [%1], 16, %2;\n"
                 :: "r"(saddr), "l"(gmem_ptr), "r"(src_bytes));
}

__global__ __launch_bounds__(256, 2) void gemm_kernel(int n_rows) {
    extern __shared__ uint32_t sm[];
    uint32_t* Asm[2] = { sm, sm + BM * LDA };
    uint32_t* Bsm[2] = { sm + 2 * BM * LDA, sm + 2 * BM * LDA + BK * LDB };

    const int tid   = threadIdx.x;
    const int lane  = tid & 31;
    const int warp  = tid >> 5;
    const int warpM = warp >> 2;   // 0..1
    const int warpN = warp & 3;    // 0..3
    const int m0 = blockIdx.y * BM;
    const int n0 = blockIdx.x * BN;

    float acc[4][4][4];
#pragma unroll
    for (int i = 0; i < 4; i++)
#pragma unroll
        for (int j = 0; j < 4; j++)
#pragma unroll
            for (int k = 0; k < 4; k++) acc[i][j][k] = 0.f;

    auto loadA = [&](int buf, int kb) {
#pragma unroll
        for (int p = 0; p < 4; p++) {
            int idx = tid + p * 256;
            int row = idx >> 3;
            int c4  = idx & 7;
            int gr  = m0 + row;
            const uint32_t* src = g_xtf + (size_t)gr * C + kb + c4 * 4;
            cp_async16(&Asm[buf][row * LDA + c4 * 4], src, gr < n_rows ? 16 : 0);
        }
    };
    auto loadB = [&](int buf, int kb) {
#pragma unroll
        for (int p = 0; p < 4; p++) {
            int idx = tid + p * 256;
            int row = idx >> 5;
            int c4  = idx & 31;
            const uint32_t* src = g_wcat + (size_t)(kb + row) * 1024 + n0 + c4 * 4;
            cp_async16(&Bsm[buf][row * LDB + c4 * 4], src, 16);
        }
    };

    loadA(0, 0); loadB(0, 0);
    asm volatile("cp.async.commit_group;\n");

#pragma unroll 1
    for (int kc = 0; kc < 8; kc++) {          // K = 256 = 8 * BK
        int cur = kc & 1;
        if (kc < 7) {
            loadA(cur ^ 1, (kc + 1) * BK);
            loadB(cur ^ 1, (kc + 1) * BK);
            asm volatile("cp.async.commit_group;\n");
            asm volatile("cp.async.wait_group 1;\n");
        } else {
            asm volatile("cp.async.wait_group 0;\n");
        }
        __syncthreads();

        const uint32_t* Ab = Asm[cur];
        const uint32_t* Bb = Bsm[cur];
#pragma unroll
        for (int kk = 0; kk < BK; kk += 8) {
            uint32_t afr[4][4];
#pragma unroll
            for (int mt = 0; mt < 4; mt++) {
                int r = warpM * 64 + mt * 16 + (lane >> 2);
                int c = kk + (lane & 3);
                afr[mt][0] = Ab[r * LDA + c];
                afr[mt][1] = Ab[(r + 8) * LDA + c];
                afr[mt][2] = Ab[r * LDA + c + 4];
                afr[mt][3] = Ab[(r + 8) * LDA + c + 4];
            }
            uint32_t bfr[4][2];
#pragma unroll
            for (int nt = 0; nt < 4; nt++) {
                int cb = warpN * 32 + nt * 8 + (lane >> 2);
                int k  = kk + (lane & 3);
                bfr[nt][0] = Bb[k * LDB + cb];
                bfr[nt][1] = Bb[(k + 4) * LDB + cb];
            }
#pragma unroll
            for (int mt = 0; mt < 4; mt++)
#pragma unroll
                for (int nt = 0; nt < 4; nt++)
                    asm volatile(
                        "mma.sync.aligned.m16n8k8.row.col.f32.tf32.tf32.f32 "
                        "{%0,%1,%2,%3}, {%4,%5,%6,%7}, {%8,%9}, {%0,%1,%2,%3};\n"
                        : "+f"(acc[mt][nt][0]), "+f"(acc[mt][nt][1]),
                          "+f"(acc[mt][nt][2]), "+f"(acc[mt][nt][3])
                        : "r"(afr[mt][0]), "r"(afr[mt][1]), "r"(afr[mt][2]), "r"(afr[mt][3]),
                          "r"(bfr[nt][0]), "r"(bfr[nt][1]));
        }
        __syncthreads();
    }

    // Epilogue: store H_s as fp16
    int s  = n0 >> 8;
    int nl = n0 & 255;
    __half* H = g_h + (size_t)s * NPAD * C;
#pragma unroll
    for (int mt = 0; mt < 4; mt++) {
        int r0 = m0 + warpM * 64 + mt * 16 + (lane >> 2);
#pragma unroll
        for (int nt = 0; nt < 4; nt++) {
            int cc = nl + warpN * 32 + nt * 8 + 2 * (lane & 3);
            if (r0 < n_rows)
                *(__half2*)&H[(size_t)r0 * C + cc] = __floats2half2_rn(acc[mt][nt][0], acc[mt][nt][1]);
            if (r0 + 8 < n_rows)
                *(__half2*)&H[(size_t)(r0 + 8) * C + cc] = __floats2half2_rn(acc[mt][nt][2], acc[mt][nt][3]);
        }
    }
}

// ---------------------------------------------------------------------------
// Aggregation: per node v, register-accumulate base + self + all CSR neighbors,
// single coalesced store. NO atomics.
// 128 threads/block, 2 channels/thread (half2 gathers).
// ---------------------------------------------------------------------------
__global__ __launch_bounds__(128) void agg_kernel(
        const float* __restrict__ x, const float* __restrict__ t0,
        const float* __restrict__ t1, const float* __restrict__ p0,
        const float* __restrict__ p1, float* __restrict__ out) {
    int v = blockIdx.x;
    int c = threadIdx.x * 2;
    float x0 = __ldg(&x[(size_t)v * C]);
    float a0 = x0 * __ldg(&t0[v]);
    float a1 = x0 * __ldg(&t1[v]);
    float accx = a0 * __ldg(&p0[c])     + a1 * __ldg(&p1[c])     + g_bsum[c];
    float accy = a0 * __ldg(&p0[c + 1]) + a1 * __ldg(&p1[c + 1]) + g_bsum[c + 1];

#pragma unroll
    for (int s = 0; s < NSETS; s++) {
        int idx = s * NN + v;
        const __half* Hs = g_h + (size_t)s * NPAD * C;
        float dv = g_dis[idx];
        // self loop: weight = dis[v]^2 = 1/deg
        {
            float2 f = __half22float2(*(const __half2*)&Hs[(size_t)v * C + c]);
            float w = dv * dv;
            accx += w * f.x;
            accy += w * f.y;
        }
        int off = g_off[idx];
        int ec  = g_deg[idx] - 1;
        int j = 0;
        for (; j + 1 < ec; j += 2) {           // 2-way MLP
            int r0 = __ldg(&g_rows[off + j]);
            int r1 = __ldg(&g_rows[off + j + 1]);
            float w0 = dv * g_dis[s * NN + r0];
            float w1 = dv * g_dis[s * NN + r1];
            float2 f0 = __half22float2(*(const __half2*)&Hs[(size_t)r0 * C + c]);
            float2 f1 = __half22float2(*(const __half2*)&Hs[(size_t)r1 * C + c]);
            accx += w0 * f0.x + w1 * f1.x;
            accy += w0 * f0.y + w1 * f1.y;
        }
        if (j < ec) {
            int r0 = __ldg(&g_rows[off + j]);
            float w0 = dv * g_dis[s * NN + r0];
            float2 f0 = __half22float2(*(const __half2*)&Hs[(size_t)r0 * C + c]);
            accx += w0 * f0.x;
            accy += w0 * f0.y;
        }
    }
    *(float2*)&out[(size_t)v * C + c] = make_float2(accx, accy);
}

// ---------------------------------------------------------------------------
extern "C" void kernel_launch(void* const* d_in, const int* in_sizes, int n_in,
                              void* d_out, int out_size) {
    const float* x   = (const float*)d_in[0];
    const int* e00   = (const int*)d_in[1];
    const int* e01   = (const int*)d_in[2];
    const int* e10   = (const int*)d_in[3];
    const int* e11   = (const int*)d_in[4];
    const float* t0  = (const float*)d_in[5];
    const float* t1  = (const float*)d_in[6];
    const float* W1  = (const float*)d_in[7];
    const float* b1  = (const float*)d_in[8];
    const float* W2  = (const float*)d_in[9];
    const float* b2  = (const float*)d_in[10];
    const float* W3  = (const float*)d_in[11];
    const float* b3  = (const float*)d_in[12];
    const float* W4  = (const float*)d_in[13];
    const float* b4  = (const float*)d_in[14];
    const float* p0  = (const float*)d_in[15];
    const float* p1  = (const float*)d_in[16];
    const float* p2  = (const float*)d_in[17];
    const float* p3  = (const float*)d_in[18];
    const float* p4  = (const float*)d_in[19];
    const float* p5  = (const float*)d_in[20];

    const int E      = in_sizes[1] / 2;      // 500000
    const int n_rows = in_sizes[0] / C;      // 100000

    cudaFuncSetAttribute(gemm_kernel, cudaFuncAttributeMaxDynamicSharedMemorySize, SMEM_BYTES);

    prep_kernel<<<256, 256>>>(W1, W2, W3, W4, b1, b2, b3, b4, p2, p3, p4, p5);

    int n4 = n_rows * C / 4;
    xcvt_kernel<<<(n4 + 255) / 256, 256>>>(x, n4);

    dim3 dgrid((E + 255) / 256, NSETS);
    deg_kernel<<<dgrid, 256>>>(e00, e01, e10, e11, E);

    dis_kernel<<<(NT + 255) / 256, 256>>>();

    scanA_kernel<<<NBLK, 256>>>();
    scanB_kernel<<<1, 512>>>();
    scanC_kernel<<<NBLK, 256>>>();

    fill_kernel<<<dgrid, 256>>>(e00, e01, e10, e11, E);

    dim3 ggrid((NSETS * C) / BN, (n_rows + BM - 1) / BM);
    gemm_kernel<<<ggrid, 256, SMEM_BYTES>>>(n_rows);

    agg_kernel<<<n_rows, 128>>>(x, t0, t1, p0, p1, (float*)d_out);
}